// round 6
// baseline (speedup 1.0000x reference)
#include <cuda_runtime.h>
#include <cstdint>
#include <math.h>

// ---------------------------------------------------------------------------
// TokenChoiceTopKRouter: logits = x @ W^T -> softmax -> top2 -> hist -> stable sort
//   x: [16384, 4096] f32, W: [64, 4096] f32
//   out (f32): [0,32768)      top_w flattened token-major
//              [32768,65536)  gather_indices (stable argsort of sel_flat)
//              [65536,65600)  num_tokens_per_expert
// ---------------------------------------------------------------------------

#define N_TOKENS 16384
#define DIM      4096
#define NE       64
#define GRID     148           // one block per SM, balanced token split
#define ROWS_PAD 112           // 16 groups x 7 tokens (>= max 111 tokens/block)
#define KC       16            // k-chunk (floats)
#define NC       (DIM / KC)    // 256 chunks
#define STR      20            // smem row stride (floats): 20*egq mod 32 distinct per octet
#define NFLAT    (N_TOKENS * 2)
#define NCHUNK   128
#define CHUNK    256

__device__ int g_sel[NFLAT];            // selected expert per (token, k) slot
__device__ int g_hist[NCHUNK * NE];     // per-chunk histograms
__device__ int g_base[NCHUNK * NE];     // per-chunk scatter bases

// ---------------- helpers ----------------
static __device__ __forceinline__ void cp16(void* sm, const void* gm) {
    unsigned s = (unsigned)__cvta_generic_to_shared(sm);
    asm volatile("cp.async.cg.shared.global [%0], [%1], 16;" :: "r"(s), "l"(gm));
}
static __device__ __forceinline__ void cp_commit() {
    asm volatile("cp.async.commit_group;");
}
template <int N>
static __device__ __forceinline__ void cp_wait() {
    asm volatile("cp.async.wait_group %0;" :: "n"(N));
}
// packed dual-fp32 FMA (FFMA2) — PTX-only path on sm_103a
static __device__ __forceinline__ void ffma2(unsigned long long& d,
                                             unsigned long long a,
                                             unsigned long long b) {
    asm("fma.rn.f32x2 %0, %1, %2, %0;" : "+l"(d) : "l"(a), "l"(b));
}
union PackU { unsigned long long u; float2 f; };

static __device__ __forceinline__ bool better(float va, int ia, float vb, int ib) {
    // "a beats b": larger value wins; tie -> smaller expert index wins
    return (va > vb) || (va == vb && ia < ib);
}

// ---------------- fused GEMM + softmax + top2 ----------------
// 256 threads. Thread (tg, egq): tokens tg*7..tg*7+6 (local), experts egq*4..egq*4+3.
// W smem: expert e stored at row (e>>2) + (e&3)*16  -> conflict-free LDS.128 reads.
__global__ void __launch_bounds__(256, 1)
gemm_router(const float* __restrict__ x, const float* __restrict__ W,
            float* __restrict__ out) {
    __shared__ float xs[3][ROWS_PAD * STR];  // 3 * 112*20*4 = 26880 B
    __shared__ float ws[3][NE * STR];        // 3 *  64*20*4 = 15360 B

    const int tid = threadIdx.x;
    const int bid = blockIdx.x;
    const int t0  = (bid * N_TOKENS) / GRID;         // balanced split: 110 or 111 tokens
    const int t1  = ((bid + 1) * N_TOKENS) / GRID;
    const int cnt = t1 - t0;
    const int tg  = tid >> 4;   // token group 0..15 (7 tokens each)
    const int egq = tid & 15;   // expert group 0..15 (4 experts each)

    // per-thread cp.async sources/dests (row-clamped so padded rows duplicate)
    const int rx = tid >> 2, c4 = tid & 3;
    const int row0 = rx;              // rows 0..63
    const int row1 = rx + 64;         // rows 64..111 (only rx < 48)
    const float* gx0 = x + (size_t)(t0 + min(row0, cnt - 1)) * DIM + c4 * 4;
    const float* gx1 = x + (size_t)(t0 + min(row1, cnt - 1)) * DIM + c4 * 4;
    const float* gw  = W + (size_t)rx * DIM + c4 * 4;            // expert rx
    const int o_x0 = row0 * STR + c4 * 4;
    const int o_x1 = row1 * STR + c4 * 4;
    const int o_w  = ((rx >> 2) + (rx & 3) * 16) * STR + c4 * 4; // permuted W row
    const bool do1 = (row1 < ROWS_PAD);

    unsigned long long acc[7][4];
#pragma unroll
    for (int i = 0; i < 7; ++i)
#pragma unroll
        for (int r = 0; r < 4; ++r) acc[i][r] = 0ull;

    auto load_chunk = [&](int c) {
        const int b = c % 3;
        const int kc = c * KC;
        cp16(&xs[b][o_x0], gx0 + kc);
        if (do1) cp16(&xs[b][o_x1], gx1 + kc);
        cp16(&ws[b][o_w], gw + kc);
        cp_commit();
    };

    load_chunk(0);
    load_chunk(1);
    for (int c = 0; c < NC; ++c) {
        if (c + 1 < NC) cp_wait<1>();   // chunk c complete (c+1 may be in flight)
        else            cp_wait<0>();
        __syncthreads();                // (a) chunk c visible to all warps
                                        // (b) everyone finished compute of c-1
        if (c + 2 < NC) load_chunk(c + 2);  // safe: c-1's buffer is free (see (b))

        const int b = c % 3;
        const float* xb = &xs[b][0];
        const float* wb = &ws[b][0];
#pragma unroll
        for (int kk = 0; kk < KC; kk += 4) {
            ulonglong2 wv[4];
#pragma unroll
            for (int r = 0; r < 4; ++r)
                wv[r] = *(const ulonglong2*)&wb[(egq + r * 16) * STR + kk];
            ulonglong2 xv[7];
#pragma unroll
            for (int i = 0; i < 7; ++i)
                xv[i] = *(const ulonglong2*)&xb[(tg * 7 + i) * STR + kk];
#pragma unroll
            for (int i = 0; i < 7; ++i)
#pragma unroll
                for (int r = 0; r < 4; ++r) {
                    ffma2(acc[i][r], xv[i].x, wv[r].x);
                    ffma2(acc[i][r], xv[i].y, wv[r].y);
                }
        }
    }

    // ---- epilogue: per token, softmax + top2 across 16-lane groups ----
    const unsigned mask = 0xffffffffu;
#pragma unroll
    for (int i = 0; i < 7; ++i) {
        float lg[4];
#pragma unroll
        for (int r = 0; r < 4; ++r) {
            PackU p; p.u = acc[i][r];
            lg[r] = p.f.x + p.f.y;
        }
        const int lt = tg * 7 + i;       // local token index (may exceed cnt-1)

        // group max over 64 experts (16 lanes x 4)
        float m = fmaxf(fmaxf(lg[0], lg[1]), fmaxf(lg[2], lg[3]));
#pragma unroll
        for (int s = 1; s < 16; s <<= 1) m = fmaxf(m, __shfl_xor_sync(mask, m, s));

        // group sum of exp
        float se = expf(lg[0] - m) + expf(lg[1] - m) + expf(lg[2] - m) + expf(lg[3] - m);
#pragma unroll
        for (int s = 1; s < 16; s <<= 1) se += __shfl_xor_sync(mask, se, s);

        // local top2 (ascending expert index -> first occurrence wins ties)
        float v1 = lg[0], v2 = -INFINITY;
        int   i1 = egq * 4, i2 = NE;
#pragma unroll
        for (int r = 1; r < 4; ++r) {
            const float v = lg[r];
            const int   e = egq * 4 + r;
            if (v > v1)      { v2 = v1; i2 = i1; v1 = v; i1 = e; }
            else if (v > v2) { v2 = v;  i2 = e; }
        }
        // merge across the 16-lane group
#pragma unroll
        for (int s = 1; s < 16; s <<= 1) {
            float ov1 = __shfl_xor_sync(mask, v1, s);
            int   oi1 = __shfl_xor_sync(mask, i1, s);
            float ov2 = __shfl_xor_sync(mask, v2, s);
            int   oi2 = __shfl_xor_sync(mask, i2, s);
            if (better(ov1, oi1, v1, i1)) {
                if (better(v1, i1, ov2, oi2)) { v2 = v1; i2 = i1; }
                else                          { v2 = ov2; i2 = oi2; }
                v1 = ov1; i1 = oi1;
            } else if (better(ov1, oi1, v2, i2)) {
                v2 = ov1; i2 = oi1;
            }
        }

        if (egq == 0 && lt < cnt) {
            const int t = t0 + lt;
            out[2 * t]     = expf(v1 - m) / se;
            out[2 * t + 1] = expf(v2 - m) / se;
            g_sel[2 * t]     = i1;
            g_sel[2 * t + 1] = i2;
        }
    }
}

// ---------------- stable counting sort of g_sel (32768 keys, 64 bins) -------
__global__ void hist_k() {
    __shared__ int h[NE];
    const int tid = threadIdx.x, c = blockIdx.x;
    if (tid < NE) h[tid] = 0;
    __syncthreads();
    atomicAdd(&h[g_sel[c * CHUNK + tid]], 1);
    __syncthreads();
    if (tid < NE) g_hist[c * NE + tid] = h[tid];
}

__global__ void scan_k(float* __restrict__ out_counts) {
    __shared__ int tot[NE];
    const int e = threadIdx.x;
    int s = 0;
    for (int c = 0; c < NCHUNK; ++c) s += g_hist[c * NE + e];
    tot[e] = s;
    out_counts[e] = (float)s;
    __syncthreads();
    int off = 0;
    for (int j = 0; j < e; ++j) off += tot[j];
    for (int c = 0; c < NCHUNK; ++c) {
        g_base[c * NE + e] = off;
        off += g_hist[c * NE + e];
    }
}

__global__ void scatter_k(float* __restrict__ out_gather) {
    __shared__ int s[CHUNK];
    const int tid = threadIdx.x, c = blockIdx.x;
    const int gi = c * CHUNK + tid;
    const int e = g_sel[gi];
    s[tid] = e;
    __syncthreads();
    int rank = 0;
    for (int j = 0; j < tid; ++j) rank += (s[j] == e);
    out_gather[g_base[c * NE + e] + rank] = (float)gi;
}

// ---------------- launch ----------------
extern "C" void kernel_launch(void* const* d_in, const int* in_sizes, int n_in,
                              void* d_out, int out_size) {
    // identify x (big) vs W (small) by element count for robustness
    const float* x;
    const float* W;
    if (in_sizes[0] > in_sizes[1]) { x = (const float*)d_in[0]; W = (const float*)d_in[1]; }
    else                           { x = (const float*)d_in[1]; W = (const float*)d_in[0]; }
    float* out = (float*)d_out;

    gemm_router<<<GRID, 256>>>(x, W, out);
    hist_k<<<NCHUNK, CHUNK>>>();
    scan_k<<<1, NE>>>(out + 2 * NFLAT);        // counts at [65536,65600)
    scatter_k<<<NCHUNK, CHUNK>>>(out + NFLAT); // gather_indices at [32768,65536)
}

// round 14
// speedup vs baseline: 2.3358x; 2.3358x over previous
#include <cuda_runtime.h>
#include <cuda_fp16.h>
#include <cstdint>
#include <math.h>

// ---------------------------------------------------------------------------
// TokenChoiceTopKRouter via mma.sync (HMMA) fp16 2-level split, 3 terms.
// Baseline-PTX only (harness targets plain sm_103: NO tcgen05).
//   logits = x @ W^T -> softmax -> top2 -> hist -> stable argsort
//   x: [16384, 4096] f32, W: [64, 4096] f32
//   out (f32): [0,32768) top_w | [32768,65536) gather_indices | [65536,65600) counts
// ---------------------------------------------------------------------------

#define N_TOKENS 16384
#define DIM      4096
#define NE       64
#define GRID_G   128            // CTAs; 128 tokens each (8 warps x m16)
#define KC       64             // f32 per k-chunk (4 k16 MMA steps)
#define NCH      (DIM / KC)     // 64 chunks
#define NFLAT    (N_TOKENS * 2)
#define NCHUNK   128
#define CHUNK    256

// smem: xs[2][128][72] f32 | wf[2][2 split][4 k16][8 nt][32 lane][2] u32
#define XSTR       72
#define XBUF       (128 * XSTR * 4)       // 36864 B per buffer
#define WF_OFF     (2 * XBUF)             // 73728
#define WBUF       16384                  // per buffer (2 splits x 8192)
#define SMEM_TOTAL (WF_OFF + 2 * WBUF)    // 106496

__device__ int g_sel[NFLAT];
__device__ int g_hist[NCHUNK * NE];
__device__ int g_base[NCHUNK * NE];
// pre-split W fragment images: [split][k16 block][nt*64 + lane*2 + reg] u32
__device__ __align__(16) unsigned g_Wfrag[2][256][512];   // 1 MB

// ---------------- helpers ----------------
static __device__ __forceinline__ unsigned smem_u32(const void* p) {
    unsigned a;
    asm("{ .reg .u64 t; cvta.to.shared.u64 t, %1; cvt.u32.u64 %0, t; }" : "=r"(a) : "l"(p));
    return a;
}
static __device__ __forceinline__ void cp16(unsigned s, const void* g) {
    asm volatile("cp.async.cg.shared.global [%0], [%1], 16;" :: "r"(s), "l"(g));
}
#define CP_COMMIT() asm volatile("cp.async.commit_group;")
#define CP_WAIT1()  asm volatile("cp.async.wait_group 1;" ::: "memory")
#define CP_WAIT0()  asm volatile("cp.async.wait_group 0;" ::: "memory")

static __device__ __forceinline__ float2 lds64f(unsigned a) {
    float2 r;
    asm volatile("ld.shared.v2.f32 {%0,%1}, [%2];" : "=f"(r.x), "=f"(r.y) : "r"(a));
    return r;
}
static __device__ __forceinline__ void lds64u(unsigned& u0, unsigned& u1, unsigned a) {
    asm volatile("ld.shared.v2.u32 {%0,%1}, [%2];" : "=r"(u0), "=r"(u1) : "r"(a));
}
// m16n8k16 f16 HMMA with fp32 accumulate (baseline PTX, sm_80+)
static __device__ __forceinline__ void mma16816(float* d, const unsigned* a,
                                                unsigned b0, unsigned b1) {
    asm volatile(
        "mma.sync.aligned.m16n8k16.row.col.f32.f16.f16.f32 "
        "{%0,%1,%2,%3}, {%4,%5,%6,%7}, {%8,%9}, {%0,%1,%2,%3};"
        : "+f"(d[0]), "+f"(d[1]), "+f"(d[2]), "+f"(d[3])
        : "r"(a[0]), "r"(a[1]), "r"(a[2]), "r"(a[3]), "r"(b0), "r"(b1));
}

union H2U { __half2 h; unsigned u; };
// split float2 into 2 fp16x2 levels (h1 + h2 captures ~22 mantissa bits)
static __device__ __forceinline__ void split2(float2 f, unsigned& u1, unsigned& u2) {
    H2U a, b;
    a.h = __float22half2_rn(f);
    float2 g = __half22float2(a.h);
    b.h = __float22half2_rn(make_float2(f.x - g.x, f.y - g.y));
    u1 = a.u; u2 = b.u;
}

static __device__ __forceinline__ bool better(float va, int ia, float vb, int ib) {
    return (va > vb) || (va == vb && ia < ib);
}

// ---------------- pre-pass: W -> per-lane B-fragment images (scaled 2^10) ----
__global__ void w_split_k(const float* __restrict__ W) {
    const int blk = blockIdx.x;            // k16 block 0..255
    const int tid = threadIdx.x;           // 256 = 8 nt x 32 lanes
    const int nt = tid >> 5, l = tid & 31;
    const int gid = l >> 2, tig = l & 3;
    const int e = nt * 8 + gid;
    const size_t base = (size_t)e * DIM + blk * 16 + tig * 2;
    const float s = 1024.0f;
    float w00 = W[base] * s,     w01 = W[base + 1] * s;
    float w10 = W[base + 8] * s, w11 = W[base + 9] * s;
    unsigned b0s1, b0s2, b1s1, b1s2;
    split2(make_float2(w00, w01), b0s1, b0s2);   // b0: k pair
    split2(make_float2(w10, w11), b1s1, b1s2);   // b1: k+8 pair
    g_Wfrag[0][blk][nt * 64 + l * 2 + 0] = b0s1;
    g_Wfrag[0][blk][nt * 64 + l * 2 + 1] = b1s1;
    g_Wfrag[1][blk][nt * 64 + l * 2 + 0] = b0s2;
    g_Wfrag[1][blk][nt * 64 + l * 2 + 1] = b1s2;
}

// ---------------- main: HMMA GEMM + softmax + top2 ----------------
__global__ void __launch_bounds__(256, 1)
gemm_router_hmma(const float* __restrict__ x, float* __restrict__ out) {
    extern __shared__ char smem[];
    const unsigned sb = smem_u32(smem);
    const int tid = threadIdx.x;
    const int w = tid >> 5, l = tid & 31;
    const int gid = l >> 2, tig = l & 3;
    const int tok0 = blockIdx.x * 128;

    float acc[8][4];
#pragma unroll
    for (int nt = 0; nt < 8; ++nt)
#pragma unroll
        for (int r = 0; r < 4; ++r) acc[nt][r] = 0.f;

    auto load_chunk = [&](int c) {
        const int buf = c & 1;
#pragma unroll
        for (int i = 0; i < 8; ++i) {           // x: 2048 float4
            const int f4 = tid + i * 256;
            const int row = f4 >> 4, c4 = (f4 & 15) * 4;
            cp16(sb + buf * XBUF + (row * XSTR + c4) * 4,
                 x + (size_t)(tok0 + row) * DIM + c * KC + c4);
        }
#pragma unroll
        for (int s = 0; s < 2; ++s)             // W frags: 2 x 8192B
#pragma unroll
            for (int i = 0; i < 2; ++i) {
                const int idx = tid + i * 256;
                cp16(sb + WF_OFF + buf * WBUF + s * 8192 + idx * 16,
                     (const char*)g_Wfrag + s * 524288 + c * 8192 + idx * 16);
            }
        CP_COMMIT();
    };

    load_chunk(0);
    for (int c = 0; c < NCH; ++c) {
        if (c + 1 < NCH) { load_chunk(c + 1); CP_WAIT1(); }
        else             { CP_WAIT0(); }
        __syncthreads();                        // chunk c visible

        const int buf = c & 1;
        const unsigned xbase = sb + buf * XBUF + ((w * 16 + gid) * XSTR) * 4;
        const unsigned wbase = sb + WF_OFF + buf * WBUF + l * 8;
#pragma unroll
        for (int ks = 0; ks < 4; ++ks) {
            const unsigned xk = xbase + (ks * 16 + tig * 2) * 4;
            float2 a00 = lds64f(xk);                       // row gid,   k pair
            float2 a10 = lds64f(xk + 8 * XSTR * 4);        // row gid+8, k pair
            float2 a01 = lds64f(xk + 32);                  // row gid,   k+8
            float2 a11 = lds64f(xk + 8 * XSTR * 4 + 32);   // row gid+8, k+8
            unsigned A1[4], A2[4];
            split2(a00, A1[0], A2[0]);
            split2(a10, A1[1], A2[1]);
            split2(a01, A1[2], A2[2]);
            split2(a11, A1[3], A2[3]);
#pragma unroll
            for (int nt = 0; nt < 8; ++nt) {
                unsigned b0a, b1a, b0b, b1b;
                lds64u(b0a, b1a, wbase + ks * 2048 + nt * 256);         // w1
                lds64u(b0b, b1b, wbase + 8192 + ks * 2048 + nt * 256);  // w2
                mma16816(acc[nt], A1, b0a, b1a);   // h1*w1
                mma16816(acc[nt], A1, b0b, b1b);   // h1*w2
                mma16816(acc[nt], A2, b0a, b1a);   // h2*w1
            }
        }
        __syncthreads();                        // all done before buf overwrite
    }

    // ---- epilogue: quad (4 lanes) owns rows gid and gid+8; 16 logits/lane ----
    const unsigned mask = 0xffffffffu;
    const float INV = 9.765625e-4f;             // 2^-10 (undo W scale, exact)
#pragma unroll
    for (int half = 0; half < 2; ++half) {
        const int t = tok0 + w * 16 + gid + half * 8;
        float v[16];
        float m = -INFINITY;
#pragma unroll
        for (int nt = 0; nt < 8; ++nt) {
            v[nt * 2]     = acc[nt][half * 2]     * INV;
            v[nt * 2 + 1] = acc[nt][half * 2 + 1] * INV;
            m = fmaxf(m, fmaxf(v[nt * 2], v[nt * 2 + 1]));
        }
#pragma unroll
        for (int s = 1; s < 4; s <<= 1) m = fmaxf(m, __shfl_xor_sync(mask, m, s));

        float se = 0.f;
#pragma unroll
        for (int i = 0; i < 16; ++i) se += expf(v[i] - m);
#pragma unroll
        for (int s = 1; s < 4; s <<= 1) se += __shfl_xor_sync(mask, se, s);

        // local top2 (indices ascending within lane -> first-wins tie ok)
        float v1 = -INFINITY, v2 = -INFINITY;
        int i1 = NE, i2 = NE;
#pragma unroll
        for (int nt = 0; nt < 8; ++nt)
#pragma unroll
            for (int j = 0; j < 2; ++j) {
                const float val = v[nt * 2 + j];
                const int e = nt * 8 + tig * 2 + j;
                if (val > v1)      { v2 = v1; i2 = i1; v1 = val; i1 = e; }
                else if (val > v2) { v2 = val; i2 = e; }
            }
        // merge across quad
#pragma unroll
        for (int s = 1; s < 4; s <<= 1) {
            float ov1 = __shfl_xor_sync(mask, v1, s);
            int   oi1 = __shfl_xor_sync(mask, i1, s);
            float ov2 = __shfl_xor_sync(mask, v2, s);
            int   oi2 = __shfl_xor_sync(mask, i2, s);
            if (better(ov1, oi1, v1, i1)) {
                if (better(v1, i1, ov2, oi2)) { v2 = v1; i2 = i1; }
                else                          { v2 = ov2; i2 = oi2; }
                v1 = ov1; i1 = oi1;
            } else if (better(ov1, oi1, v2, i2)) {
                v2 = ov1; i2 = oi1;
            }
        }
        if (tig == 0) {
            out[2 * t]     = expf(v1 - m) / se;
            out[2 * t + 1] = expf(v2 - m) / se;
            g_sel[2 * t]     = i1;
            g_sel[2 * t + 1] = i2;
        }
    }
}

// ---------------- stable counting sort of g_sel (32768 keys, 64 bins) -------
__global__ void hist_k() {
    __shared__ int h[NE];
    const int tid = threadIdx.x, c = blockIdx.x;
    if (tid < NE) h[tid] = 0;
    __syncthreads();
    atomicAdd(&h[g_sel[c * CHUNK + tid]], 1);
    __syncthreads();
    if (tid < NE) g_hist[c * NE + tid] = h[tid];
}

__global__ void scan_k(float* __restrict__ out_counts) {
    __shared__ int tot[NE];
    const int e = threadIdx.x;
    int s = 0;
    for (int c = 0; c < NCHUNK; ++c) s += g_hist[c * NE + e];
    tot[e] = s;
    out_counts[e] = (float)s;
    __syncthreads();
    int off = 0;
    for (int j = 0; j < e; ++j) off += tot[j];
    for (int c = 0; c < NCHUNK; ++c) {
        g_base[c * NE + e] = off;
        off += g_hist[c * NE + e];
    }
}

__global__ void scatter_k(float* __restrict__ out_gather) {
    __shared__ int wcnt[8][NE];
    const int tid = threadIdx.x, c = blockIdx.x;
    const int w = tid >> 5, l = tid & 31;
    for (int i = tid; i < 8 * NE; i += 256) ((int*)wcnt)[i] = 0;
    __syncthreads();
    const int gi = c * CHUNK + tid;
    const int e = g_sel[gi];
    const unsigned m = __match_any_sync(0xffffffffu, e);
    const int lanerank = __popc(m & ((1u << l) - 1));
    if (l == (__ffs(m) - 1)) wcnt[w][e] = __popc(m);
    __syncthreads();
    int base = 0;
    for (int ww = 0; ww < w; ++ww) base += wcnt[ww][e];
    out_gather[g_base[c * NE + e] + base + lanerank] = (float)gi;
}

// ---------------- launch ----------------
extern "C" void kernel_launch(void* const* d_in, const int* in_sizes, int n_in,
                              void* d_out, int out_size) {
    const float* x;
    const float* W;
    if (in_sizes[0] > in_sizes[1]) { x = (const float*)d_in[0]; W = (const float*)d_in[1]; }
    else                           { x = (const float*)d_in[1]; W = (const float*)d_in[0]; }
    float* out = (float*)d_out;

    cudaFuncSetAttribute(gemm_router_hmma,
                         cudaFuncAttributeMaxDynamicSharedMemorySize, SMEM_TOTAL);

    w_split_k<<<256, 256>>>(W);
    gemm_router_hmma<<<GRID_G, 256, SMEM_TOTAL>>>(x, out);
    hist_k<<<NCHUNK, CHUNK>>>();
    scan_k<<<1, NE>>>(out + 2 * NFLAT);
    scatter_k<<<NCHUNK, CHUNK>>>(out + NFLAT);
}